// round 11
// baseline (speedup 1.0000x reference)
#include <cuda_runtime.h>
#include <cuda_bf16.h>
#include <cstdint>

#define Bdim 8
#define Wdim 4096
#define Rdim 128
#define Ddim 128
#define BLK  128
#define NBLK 32
#define NTHR 256

// ---------------------------------------------------------------------------
// Scratch (__device__ globals; allocation-free rule)
// ---------------------------------------------------------------------------
__device__ float g_ptab[129 * 128];   // ptab[i*128+r] = gamma_r^i
__device__ float g_ntab[128 * 128];   // ntab[j*128+r] = gamma_r^{-j}
__device__ float g_A[Bdim * NBLK * BLK * BLK];       // masked A[i][j]
__device__ float g_U[Bdim * NBLK * Ddim * Rdim];     // Ut layout [d][r]
__device__ float g_S[Bdim * NBLK * Ddim * Rdim];     // St layout [d][r]

// ---------------------------------------------------------------------------
// SMEM map (k-chunk = 32):
//  bf16 tiles: 4 x (128 rows x 80B)  = 40960   (80B row: 16B-aligned ldmatrix)
//  raw fp32 double buffers: 2 x 36864 = 73728
// ---------------------------------------------------------------------------
#define CROWB   80                      // tile row bytes (32 halves + 16 pad)
#define CTILEB  (128 * CROWB)           // 10240
#define T_AHI   0
#define T_ALO   CTILEB
#define T_BHI   (2 * CTILEB)
#define T_BLO   (3 * CTILEB)
#define RAWBUF  (4 * CTILEB)            // 40960; raw[1] = +36864
#define RAWOPB  18432                   // bytes per raw operand slot
#define NATRS   144                     // nat raw row stride (36 floats)
#define TRRS    528                     // tr  raw row stride (132 floats)
#define SMEM_TOTAL (RAWBUF + 2 * 36864) // 114688

__device__ __forceinline__ uint32_t smem_u32(const void* p) {
    uint32_t a;
    asm("{ .reg .u64 t; cvta.to.shared.u64 t, %1; cvt.u32.u64 %0, t; }" : "=r"(a) : "l"(p));
    return a;
}
__device__ __forceinline__ void cpasync16(uint32_t dst, const void* src) {
    asm volatile("cp.async.ca.shared.global [%0], [%1], 16;" :: "r"(dst), "l"(src));
}
__device__ __forceinline__ void cp_commit() {
    asm volatile("cp.async.commit_group;" ::: "memory");
}
__device__ __forceinline__ void cp_wait1() {
    asm volatile("cp.async.wait_group 1;" ::: "memory");
}
__device__ __forceinline__ void cp_wait0() {
    asm volatile("cp.async.wait_group 0;" ::: "memory");
}

__device__ __forceinline__ void split1(float a, unsigned short& h, unsigned short& l) {
    __nv_bfloat16 hb = __float2bfloat16(a);
    float rem = a - __bfloat162float(hb);
    __nv_bfloat16 lb = __float2bfloat16(rem);
    h = *(unsigned short*)&hb;
    l = *(unsigned short*)&lb;
}
__device__ __forceinline__ unsigned long long pack4(unsigned short a, unsigned short b,
                                                    unsigned short c, unsigned short d) {
    return (unsigned long long)a | ((unsigned long long)b << 16)
         | ((unsigned long long)c << 32) | ((unsigned long long)d << 48);
}

// ---------------------------------------------------------------------------
// Async issue: raw fp32 chunk -> SMEM
// nat: rows 0..127, cols [kc, kc+32)
// ---------------------------------------------------------------------------
__device__ __forceinline__ void issue_nat(const float* __restrict__ src, int kc,
                                          uint32_t raw, int tid) {
#pragma unroll
    for (int it = 0; it < 4; it++) {
        int t = tid + it * NTHR;            // 0..1023
        int row = t >> 3, c4 = (t & 7) << 2;
        cpasync16(raw + row * NATRS + c4 * 4, src + row * 128 + kc + c4);
    }
}
// tr: source rows [jc, jc+32), all 128 cols
__device__ __forceinline__ void issue_tr(const float* __restrict__ src, int jc,
                                         uint32_t raw, int tid) {
#pragma unroll
    for (int it = 0; it < 4; it++) {
        int t = tid + it * NTHR;            // 0..1023
        int j = t >> 5, c4 = (t & 31) << 2;
        cpasync16(raw + j * TRRS + c4 * 4, src + (jc + j) * 128 + c4);
    }
}

// ---------------------------------------------------------------------------
// Convert raw -> bf16 hi/lo tiles (SMEM->SMEM, weights via LDG (L2-hot))
// ---------------------------------------------------------------------------
__device__ __forceinline__ void conv_nat(const char* raw, const float* __restrict__ wt,
                                         int wrofs, int kc, char* hiT, char* loT, int tid) {
#pragma unroll
    for (int it = 0; it < 4; it++) {
        int t = tid + it * NTHR;
        int row = t >> 3, c4 = (t & 7) << 2;
        float4 v = *(const float4*)(raw + row * NATRS + c4 * 4);
        if (wt) {
            float4 w = *(const float4*)(wt + (row + wrofs) * 128 + kc + c4);
            v.x *= w.x; v.y *= w.y; v.z *= w.z; v.w *= w.w;
        }
        unsigned short h[4], l[4];
        split1(v.x, h[0], l[0]); split1(v.y, h[1], l[1]);
        split1(v.z, h[2], l[2]); split1(v.w, h[3], l[3]);
        int off = row * CROWB + c4 * 2;
        *(unsigned long long*)(hiT + off) = pack4(h[0], h[1], h[2], h[3]);
        *(unsigned long long*)(loT + off) = pack4(l[0], l[1], l[2], l[3]);
    }
}
// tr: tile[c][j-jc] = raw[j-jc][c] * (useW ? ptab[(127-j)*128+c] : 1)
__device__ __forceinline__ void conv_tr(const char* raw, bool useW, int jc,
                                        char* hiT, char* loT, int tid) {
    int jblk = tid >> 5, c0 = (tid & 31) << 2;   // 8 jblks x 32 c-groups
    unsigned short hs[4][4], ls[4][4];
#pragma unroll
    for (int x = 0; x < 4; x++) {
        int jl = jblk * 4 + x;
        float4 v = *(const float4*)(raw + jl * TRRS + c0 * 4);
        if (useW) {
            float4 w = *(const float4*)(g_ptab + (127 - (jc + jl)) * 128 + c0);
            v.x *= w.x; v.y *= w.y; v.z *= w.z; v.w *= w.w;
        }
        split1(v.x, hs[x][0], ls[x][0]); split1(v.y, hs[x][1], ls[x][1]);
        split1(v.z, hs[x][2], ls[x][2]); split1(v.w, hs[x][3], ls[x][3]);
    }
#pragma unroll
    for (int u = 0; u < 4; u++) {
        int off = (c0 + u) * CROWB + jblk * 8;
        *(unsigned long long*)(hiT + off) = pack4(hs[0][u], hs[1][u], hs[2][u], hs[3][u]);
        *(unsigned long long*)(loT + off) = pack4(ls[0][u], ls[1][u], ls[2][u], ls[3][u]);
    }
}

// ---------------------------------------------------------------------------
// mma.sync core: 8 warps, warp tile 32x64, fused bf16x3, k-chunk 32
// ---------------------------------------------------------------------------
__device__ __forceinline__ void ldsm_x4(uint32_t addr, uint32_t& r0, uint32_t& r1,
                                        uint32_t& r2, uint32_t& r3) {
    asm volatile("ldmatrix.sync.aligned.m8n8.x4.shared.b16 {%0,%1,%2,%3}, [%4];"
                 : "=r"(r0), "=r"(r1), "=r"(r2), "=r"(r3) : "r"(addr));
}
__device__ __forceinline__ void mma16816(float* c, const uint32_t a[4],
                                         uint32_t b0, uint32_t b1) {
    asm volatile("mma.sync.aligned.m16n8k16.row.col.f32.bf16.bf16.f32 "
                 "{%0,%1,%2,%3}, {%4,%5,%6,%7}, {%8,%9}, {%0,%1,%2,%3};"
                 : "+f"(c[0]), "+f"(c[1]), "+f"(c[2]), "+f"(c[3])
                 : "r"(a[0]), "r"(a[1]), "r"(a[2]), "r"(a[3]), "r"(b0), "r"(b1));
}

__device__ __forceinline__ void gemm32(const char* smem, int m0, int n0, int lane,
                                       float acc[2][8][4]) {
    uint32_t AHI = smem_u32(smem) + T_AHI;
    uint32_t ALO = smem_u32(smem) + T_ALO;
    uint32_t BHI = smem_u32(smem) + T_BHI;
    uint32_t BLO = smem_u32(smem) + T_BLO;
    int r = lane & 7, sub = lane >> 3;
    int aRow = (sub & 1) * 8 + r, aK = (sub >> 1) * 8;
    int bRow = (sub >> 1) * 8 + r, bK = (sub & 1) * 8;
#pragma unroll
    for (int ks = 0; ks < 2; ks++) {
        int k0 = ks * 16;
        uint32_t ahi[2][4], alo[2][4];
#pragma unroll
        for (int am = 0; am < 2; am++) {
            uint32_t base = (uint32_t)((m0 + am * 16 + aRow) * CROWB + (k0 + aK) * 2);
            ldsm_x4(AHI + base, ahi[am][0], ahi[am][1], ahi[am][2], ahi[am][3]);
            ldsm_x4(ALO + base, alo[am][0], alo[am][1], alo[am][2], alo[am][3]);
        }
#pragma unroll
        for (int g = 0; g < 4; g++) {
            uint32_t base = (uint32_t)((n0 + g * 16 + bRow) * CROWB + (k0 + bK) * 2);
            uint32_t bh0, bh1, bh2, bh3, bl0, bl1, bl2, bl3;
            ldsm_x4(BHI + base, bh0, bh1, bh2, bh3);
            ldsm_x4(BLO + base, bl0, bl1, bl2, bl3);
#pragma unroll
            for (int am = 0; am < 2; am++) {
                mma16816(acc[am][g * 2 + 0], ahi[am], bh0, bh1);
                mma16816(acc[am][g * 2 + 1], ahi[am], bh2, bh3);
                mma16816(acc[am][g * 2 + 0], ahi[am], bl0, bl1);
                mma16816(acc[am][g * 2 + 1], ahi[am], bl2, bl3);
                mma16816(acc[am][g * 2 + 0], alo[am], bh0, bh1);
                mma16816(acc[am][g * 2 + 1], alo[am], bh2, bh3);
            }
        }
    }
}

__device__ __forceinline__ void zero_acc(float acc[2][8][4]) {
#pragma unroll
    for (int am = 0; am < 2; am++)
#pragma unroll
        for (int g = 0; g < 8; g++)
#pragma unroll
            for (int e = 0; e < 4; e++) acc[am][g][e] = 0.f;
}

__device__ __forceinline__ void epilogue(float acc[2][8][4], float* __restrict__ dst,
                                         bool mask, int m0, int n0, int lane) {
    int t4 = lane >> 2, tp2 = (lane & 3) * 2;
#pragma unroll
    for (int am = 0; am < 2; am++) {
#pragma unroll
        for (int g = 0; g < 8; g++) {
            int col = n0 + g * 8 + tp2;
            int row0 = m0 + am * 16 + t4;
            float c0 = acc[am][g][0], c1 = acc[am][g][1];
            float c2 = acc[am][g][2], c3 = acc[am][g][3];
            if (mask) {
                if (row0 < col)         c0 = 0.f;
                if (row0 < col + 1)     c1 = 0.f;
                if (row0 + 8 < col)     c2 = 0.f;
                if (row0 + 8 < col + 1) c3 = 0.f;
            }
            *(float2*)(dst + row0 * 128 + col)       = make_float2(c0, c1);
            *(float2*)(dst + (row0 + 8) * 128 + col) = make_float2(c2, c3);
        }
    }
}

// ---------------------------------------------------------------------------
// Power tables
// ---------------------------------------------------------------------------
__global__ void pow_kernel(const float* __restrict__ gamma) {
    int r = threadIdx.x, row = blockIdx.x;
    float lg = logf(gamma[r]);
    if (row < 129) g_ptab[row * 128 + r] = expf((float)row * lg);
    else           g_ntab[(row - 129) * 128 + r] = expf(-(float)(row - 129) * lg);
}

// ---------------------------------------------------------------------------
// Phase 1 (z=0): A = mask((QΓ)(KΓ')^T); (z=1): Ut[d,r] — pipelined, 4 chunks
// ---------------------------------------------------------------------------
__global__ __launch_bounds__(NTHR, 2) void matAU_kernel(const float* __restrict__ q,
                                                        const float* __restrict__ k,
                                                        const float* __restrict__ h) {
    extern __shared__ __align__(16) char smem[];
    uint32_t sb = smem_u32(smem);
    int n = blockIdx.x, b = blockIdx.y;
    int tid = threadIdx.x, wid = tid >> 5, lane = tid & 31;
    int m0 = (wid & 3) * 32, n0 = (wid >> 2) * 64;

    const int in_base = (b * Wdim + n * BLK) * Rdim;
    const bool zA = (blockIdx.z == 0);
    float acc[2][8][4];
    zero_acc(acc);

    // issue chunk 0
    {
        uint32_t rA = sb + RAWBUF, rB = rA + RAWOPB;
        if (zA) { issue_nat(q + in_base, 0, rA, tid); issue_nat(k + in_base, 0, rB, tid); }
        else    { issue_tr(h + in_base, 0, rA, tid);  issue_tr(k + in_base, 0, rB, tid); }
        cp_commit();
    }
#pragma unroll
    for (int c = 0; c < 4; c++) {
        if (c + 1 < 4) {
            uint32_t base = sb + RAWBUF + ((c + 1) & 1) * 36864;
            uint32_t rA = base, rB = base + RAWOPB;
            int kc = (c + 1) * 32;
            if (zA) { issue_nat(q + in_base, kc, rA, tid); issue_nat(k + in_base, kc, rB, tid); }
            else    { issue_tr(h + in_base, kc, rA, tid);  issue_tr(k + in_base, kc, rB, tid); }
            cp_commit();
            cp_wait1();
        } else {
            cp_wait0();
        }
        __syncthreads();
        {
            const char* base = smem + RAWBUF + (c & 1) * 36864;
            int kc = c * 32;
            if (zA) {
                conv_nat(base, g_ptab, 0, kc, smem + T_AHI, smem + T_ALO, tid);
                conv_nat(base + RAWOPB, g_ntab, 0, kc, smem + T_BHI, smem + T_BLO, tid);
            } else {
                conv_tr(base, false, kc, smem + T_AHI, smem + T_ALO, tid);
                conv_tr(base + RAWOPB, true, kc, smem + T_BHI, smem + T_BLO, tid);
            }
        }
        __syncthreads();
        gemm32(smem, m0, n0, lane, acc);
        __syncthreads();
    }

    if (zA) epilogue(acc, g_A + (b * NBLK + n) * (BLK * BLK), true, m0, n0, lane);
    else    epilogue(acc, g_U + (b * NBLK + n) * (Ddim * Rdim), false, m0, n0, lane);
}

// ---------------------------------------------------------------------------
// Phase 2: prefix scan on [d][r] state, MLP-32 preload
// ---------------------------------------------------------------------------
__global__ void scan_kernel() {
    int gid = blockIdx.x * 256 + threadIdx.x;   // 131072
    int b = gid >> 14, dr = gid & 16383, r = dr & 127;
    float gdec = g_ptab[128 * 128 + r];         // gamma_r^128
    int base = b * NBLK * 16384 + dr;
    float u[NBLK];
#pragma unroll
    for (int nn = 0; nn < NBLK; nn++) u[nn] = g_U[base + nn * 16384];
    float s = 0.f;
#pragma unroll
    for (int nn = 0; nn < NBLK; nn++) {
        g_S[base + nn * 16384] = s;
        s = fmaf(s, gdec, u[nn]);
    }
}

// ---------------------------------------------------------------------------
// Phase 3: out = A @ H + (Q*g^(i+1)) @ St — one 8-chunk pipelined loop
// ---------------------------------------------------------------------------
__global__ __launch_bounds__(NTHR, 2) void out_kernel(const float* __restrict__ q,
                                                      const float* __restrict__ h,
                                                      float* __restrict__ out) {
    extern __shared__ __align__(16) char smem[];
    uint32_t sb = smem_u32(smem);
    int n = blockIdx.x, b = blockIdx.y;
    int tid = threadIdx.x, wid = tid >> 5, lane = tid & 31;
    int m0 = (wid & 3) * 32, n0 = (wid >> 2) * 64;

    const float* Ablk = g_A + (b * NBLK + n) * (BLK * BLK);
    const float* Sblk = g_S + (b * NBLK + n) * (Ddim * Rdim);
    const float* hblk = h + (b * Wdim + n * BLK) * Ddim;
    const float* qblk = q + (b * Wdim + n * BLK) * Rdim;

    float acc[2][8][4];
    zero_acc(acc);

    // issue chunk 0 (part 1, jc=0)
    {
        uint32_t rA = sb + RAWBUF, rB = rA + RAWOPB;
        issue_nat(Ablk, 0, rA, tid);
        issue_tr(hblk, 0, rB, tid);
        cp_commit();
    }
#pragma unroll
    for (int c = 0; c < 8; c++) {
        if (c + 1 < 8) {
            int cn = c + 1;
            uint32_t base = sb + RAWBUF + (cn & 1) * 36864;
            uint32_t rA = base, rB = base + RAWOPB;
            if (cn < 4) {
                issue_nat(Ablk, cn * 32, rA, tid);
                issue_tr(hblk, cn * 32, rB, tid);
            } else {
                issue_nat(qblk, (cn - 4) * 32, rA, tid);
                issue_nat(Sblk, (cn - 4) * 32, rB, tid);
            }
            cp_commit();
            cp_wait1();
        } else {
            cp_wait0();
        }
        __syncthreads();
        {
            const char* base = smem + RAWBUF + (c & 1) * 36864;
            if (c < 4) {
                conv_nat(base, (const float*)0, 0, 0, smem + T_AHI, smem + T_ALO, tid);
                conv_tr(base + RAWOPB, false, c * 32, smem + T_BHI, smem + T_BLO, tid);
            } else {
                conv_nat(base, g_ptab, 1, (c - 4) * 32, smem + T_AHI, smem + T_ALO, tid);
                conv_nat(base + RAWOPB, (const float*)0, 0, 0, smem + T_BHI, smem + T_BLO, tid);
            }
        }
        __syncthreads();
        gemm32(smem, m0, n0, lane, acc);
        __syncthreads();
    }

    epilogue(acc, out + (b * Wdim + n * BLK) * Ddim, false, m0, n0, lane);
}

// ---------------------------------------------------------------------------
extern "C" void kernel_launch(void* const* d_in, const int* in_sizes, int n_in,
                              void* d_out, int out_size) {
    const float* q     = (const float*)d_in[0];
    const float* k     = (const float*)d_in[1];
    const float* h     = (const float*)d_in[2];
    const float* gamma = (const float*)d_in[3];
    float* out = (float*)d_out;

    cudaFuncSetAttribute(matAU_kernel, cudaFuncAttributeMaxDynamicSharedMemorySize, SMEM_TOTAL);
    cudaFuncSetAttribute(out_kernel,   cudaFuncAttributeMaxDynamicSharedMemorySize, SMEM_TOTAL);

    pow_kernel<<<257, 128>>>(gamma);
    matAU_kernel<<<dim3(NBLK, Bdim, 2), NTHR, SMEM_TOTAL>>>(q, k, h);
    scan_kernel<<<512, 256>>>();
    out_kernel<<<dim3(NBLK, Bdim), NTHR, SMEM_TOTAL>>>(q, h, out);
}

// round 12
// speedup vs baseline: 1.1516x; 1.1516x over previous
#include <cuda_runtime.h>
#include <cuda_bf16.h>
#include <cstdint>

#define Bdim 8
#define Wdim 4096
#define Rdim 128
#define Ddim 128
#define BLK  128
#define NBLK 32
#define NTHR 256

// ---------------------------------------------------------------------------
// Scratch (__device__ globals; allocation-free rule)
// ---------------------------------------------------------------------------
__device__ float g_ptab[129 * 128];   // ptab[i*128+r] = gamma_r^i
__device__ float g_ntab[128 * 128];   // ntab[j*128+r] = gamma_r^{-j}
__device__ float g_A[Bdim * NBLK * BLK * BLK];       // masked A[i][j]
__device__ float g_U[Bdim * NBLK * Ddim * Rdim];     // Ut layout [d][r]
__device__ float g_S[Bdim * NBLK * Ddim * Rdim];     // St layout [d][r]

// ---------------------------------------------------------------------------
// SMEM: DOUBLE-buffered bf16 tiles, k-chunk = 32.
// One buffer = 4 tiles x (128 rows x 80B) = 40960B. Two buffers = 81920B.
// 80B row stride: 16B-aligned ldmatrix rows, conflict-free phases.
// ---------------------------------------------------------------------------
#define CROWB   80
#define CTILEB  (128 * CROWB)           // 10240
#define T_AHI   0
#define T_ALO   CTILEB
#define T_BHI   (2 * CTILEB)
#define T_BLO   (3 * CTILEB)
#define TILBUF  (4 * CTILEB)            // 40960 per buffer
#define SMEM_TOTAL (2 * TILBUF)         // 81920 -> 2 CTAs/SM

__device__ __forceinline__ uint32_t smem_u32(const void* p) {
    uint32_t a;
    asm("{ .reg .u64 t; cvta.to.shared.u64 t, %1; cvt.u32.u64 %0, t; }" : "=r"(a) : "l"(p));
    return a;
}

__device__ __forceinline__ void split1(float a, unsigned short& h, unsigned short& l) {
    __nv_bfloat16 hb = __float2bfloat16(a);
    float rem = a - __bfloat162float(hb);
    __nv_bfloat16 lb = __float2bfloat16(rem);
    h = *(unsigned short*)&hb;
    l = *(unsigned short*)&lb;
}
__device__ __forceinline__ unsigned long long pack4(unsigned short a, unsigned short b,
                                                    unsigned short c, unsigned short d) {
    return (unsigned long long)a | ((unsigned long long)b << 16)
         | ((unsigned long long)c << 32) | ((unsigned long long)d << 48);
}

// ---------------------------------------------------------------------------
// Direct staging gmem -> bf16 hi/lo tiles (k-chunk 32)
// nat: tile[m][c] = src[m][kc+c] * (wt ? wt[(m+wrofs)*128 + kc+c] : 1)
// ---------------------------------------------------------------------------
__device__ __forceinline__ void stage_nat32(const float* __restrict__ src,
                                            const float* __restrict__ wt, int wrofs,
                                            int kc, char* hiT, char* loT, int tid) {
#pragma unroll
    for (int it = 0; it < 4; it++) {
        int t = tid + it * NTHR;            // 0..1023
        int row = t >> 3, c4 = (t & 7) << 2;
        float4 v = *(const float4*)(src + row * 128 + kc + c4);
        if (wt) {
            float4 w = *(const float4*)(wt + (row + wrofs) * 128 + kc + c4);
            v.x *= w.x; v.y *= w.y; v.z *= w.z; v.w *= w.w;
        }
        unsigned short h[4], l[4];
        split1(v.x, h[0], l[0]); split1(v.y, h[1], l[1]);
        split1(v.z, h[2], l[2]); split1(v.w, h[3], l[3]);
        int off = row * CROWB + c4 * 2;
        *(unsigned long long*)(hiT + off) = pack4(h[0], h[1], h[2], h[3]);
        *(unsigned long long*)(loT + off) = pack4(l[0], l[1], l[2], l[3]);
    }
}
// tr: tile[c][j-jc] = src[j][c] * (useW ? ptab[(127-j)*128+c] : 1), j in [jc,jc+32)
__device__ __forceinline__ void stage_tr32(const float* __restrict__ src, bool useW,
                                           int jc, char* hiT, char* loT, int tid) {
    int jblk = tid >> 5, c0 = (tid & 31) << 2;   // 8 jblks x 32 c-groups
    unsigned short hs[4][4], ls[4][4];
#pragma unroll
    for (int x = 0; x < 4; x++) {
        int j = jc + jblk * 4 + x;
        float4 v = *(const float4*)(src + j * 128 + c0);
        if (useW) {
            float4 w = *(const float4*)(g_ptab + (127 - j) * 128 + c0);
            v.x *= w.x; v.y *= w.y; v.z *= w.z; v.w *= w.w;
        }
        split1(v.x, hs[x][0], ls[x][0]); split1(v.y, hs[x][1], ls[x][1]);
        split1(v.z, hs[x][2], ls[x][2]); split1(v.w, hs[x][3], ls[x][3]);
    }
#pragma unroll
    for (int u = 0; u < 4; u++) {
        int off = (c0 + u) * CROWB + jblk * 8;
        *(unsigned long long*)(hiT + off) = pack4(hs[0][u], hs[1][u], hs[2][u], hs[3][u]);
        *(unsigned long long*)(loT + off) = pack4(ls[0][u], ls[1][u], ls[2][u], ls[3][u]);
    }
}

// ---------------------------------------------------------------------------
// mma.sync core: 8 warps, warp tile 32x64, fused bf16x3, k-chunk 32
// ---------------------------------------------------------------------------
__device__ __forceinline__ void ldsm_x4(uint32_t addr, uint32_t& r0, uint32_t& r1,
                                        uint32_t& r2, uint32_t& r3) {
    asm volatile("ldmatrix.sync.aligned.m8n8.x4.shared.b16 {%0,%1,%2,%3}, [%4];"
                 : "=r"(r0), "=r"(r1), "=r"(r2), "=r"(r3) : "r"(addr));
}
__device__ __forceinline__ void mma16816(float* c, const uint32_t a[4],
                                         uint32_t b0, uint32_t b1) {
    asm volatile("mma.sync.aligned.m16n8k16.row.col.f32.bf16.bf16.f32 "
                 "{%0,%1,%2,%3}, {%4,%5,%6,%7}, {%8,%9}, {%0,%1,%2,%3};"
                 : "+f"(c[0]), "+f"(c[1]), "+f"(c[2]), "+f"(c[3])
                 : "r"(a[0]), "r"(a[1]), "r"(a[2]), "r"(a[3]), "r"(b0), "r"(b1));
}

__device__ __forceinline__ void gemm32(const char* buf, int m0, int n0, int lane,
                                       float acc[2][8][4]) {
    uint32_t AHI = smem_u32(buf) + T_AHI;
    uint32_t ALO = smem_u32(buf) + T_ALO;
    uint32_t BHI = smem_u32(buf) + T_BHI;
    uint32_t BLO = smem_u32(buf) + T_BLO;
    int r = lane & 7, sub = lane >> 3;
    int aRow = (sub & 1) * 8 + r, aK = (sub >> 1) * 8;
    int bRow = (sub >> 1) * 8 + r, bK = (sub & 1) * 8;
#pragma unroll
    for (int ks = 0; ks < 2; ks++) {
        int k0 = ks * 16;
        uint32_t ahi[2][4], alo[2][4];
#pragma unroll
        for (int am = 0; am < 2; am++) {
            uint32_t base = (uint32_t)((m0 + am * 16 + aRow) * CROWB + (k0 + aK) * 2);
            ldsm_x4(AHI + base, ahi[am][0], ahi[am][1], ahi[am][2], ahi[am][3]);
            ldsm_x4(ALO + base, alo[am][0], alo[am][1], alo[am][2], alo[am][3]);
        }
#pragma unroll
        for (int g = 0; g < 4; g++) {
            uint32_t base = (uint32_t)((n0 + g * 16 + bRow) * CROWB + (k0 + bK) * 2);
            uint32_t bh0, bh1, bh2, bh3, bl0, bl1, bl2, bl3;
            ldsm_x4(BHI + base, bh0, bh1, bh2, bh3);
            ldsm_x4(BLO + base, bl0, bl1, bl2, bl3);
#pragma unroll
            for (int am = 0; am < 2; am++) {
                mma16816(acc[am][g * 2 + 0], ahi[am], bh0, bh1);
                mma16816(acc[am][g * 2 + 1], ahi[am], bh2, bh3);
                mma16816(acc[am][g * 2 + 0], ahi[am], bl0, bl1);
                mma16816(acc[am][g * 2 + 1], ahi[am], bl2, bl3);
                mma16816(acc[am][g * 2 + 0], alo[am], bh0, bh1);
                mma16816(acc[am][g * 2 + 1], alo[am], bh2, bh3);
            }
        }
    }
}

__device__ __forceinline__ void zero_acc(float acc[2][8][4]) {
#pragma unroll
    for (int am = 0; am < 2; am++)
#pragma unroll
        for (int g = 0; g < 8; g++)
#pragma unroll
            for (int e = 0; e < 4; e++) acc[am][g][e] = 0.f;
}

__device__ __forceinline__ void epilogue(float acc[2][8][4], float* __restrict__ dst,
                                         bool mask, int m0, int n0, int lane) {
    int t4 = lane >> 2, tp2 = (lane & 3) * 2;
#pragma unroll
    for (int am = 0; am < 2; am++) {
#pragma unroll
        for (int g = 0; g < 8; g++) {
            int col = n0 + g * 8 + tp2;
            int row0 = m0 + am * 16 + t4;
            float c0 = acc[am][g][0], c1 = acc[am][g][1];
            float c2 = acc[am][g][2], c3 = acc[am][g][3];
            if (mask) {
                if (row0 < col)         c0 = 0.f;
                if (row0 < col + 1)     c1 = 0.f;
                if (row0 + 8 < col)     c2 = 0.f;
                if (row0 + 8 < col + 1) c3 = 0.f;
            }
            *(float2*)(dst + row0 * 128 + col)       = make_float2(c0, c1);
            *(float2*)(dst + (row0 + 8) * 128 + col) = make_float2(c2, c3);
        }
    }
}

// ---------------------------------------------------------------------------
// Power tables
// ---------------------------------------------------------------------------
__global__ void pow_kernel(const float* __restrict__ gamma) {
    int r = threadIdx.x, row = blockIdx.x;
    float lg = logf(gamma[r]);
    if (row < 129) g_ptab[row * 128 + r] = expf((float)row * lg);
    else           g_ntab[(row - 129) * 128 + r] = expf(-(float)(row - 129) * lg);
}

// ---------------------------------------------------------------------------
// Phase 1 (z=0): A = mask((QΓ)(KΓ')^T); (z=1): Ut[d,r]
// Double-buffered tiles: gemm(c) then stage(c+1) into other buffer; 1 sync/chunk
// ---------------------------------------------------------------------------
__global__ __launch_bounds__(NTHR, 2) void matAU_kernel(const float* __restrict__ q,
                                                        const float* __restrict__ k,
                                                        const float* __restrict__ h) {
    extern __shared__ __align__(16) char smem[];
    int n = blockIdx.x, b = blockIdx.y;
    int tid = threadIdx.x, wid = tid >> 5, lane = tid & 31;
    int m0 = (wid & 3) * 32, n0 = (wid >> 2) * 64;

    const int in_base = (b * Wdim + n * BLK) * Rdim;
    const bool zA = (blockIdx.z == 0);
    float acc[2][8][4];
    zero_acc(acc);

    // stage chunk 0 into buf0
    if (zA) {
        stage_nat32(q + in_base, g_ptab, 0, 0, smem + T_AHI, smem + T_ALO, tid);
        stage_nat32(k + in_base, g_ntab, 0, 0, smem + T_BHI, smem + T_BLO, tid);
    } else {
        stage_tr32(h + in_base, false, 0, smem + T_AHI, smem + T_ALO, tid);
        stage_tr32(k + in_base, true,  0, smem + T_BHI, smem + T_BLO, tid);
    }
    __syncthreads();

#pragma unroll
    for (int c = 0; c < 4; c++) {
        char* cur = smem + (c & 1) * TILBUF;
        gemm32(cur, m0, n0, lane, acc);
        if (c + 1 < 4) {
            char* nxt = smem + ((c + 1) & 1) * TILBUF;
            int kc = (c + 1) * 32;
            if (zA) {
                stage_nat32(q + in_base, g_ptab, 0, kc, nxt + T_AHI, nxt + T_ALO, tid);
                stage_nat32(k + in_base, g_ntab, 0, kc, nxt + T_BHI, nxt + T_BLO, tid);
            } else {
                stage_tr32(h + in_base, false, kc, nxt + T_AHI, nxt + T_ALO, tid);
                stage_tr32(k + in_base, true,  kc, nxt + T_BHI, nxt + T_BLO, tid);
            }
        }
        __syncthreads();
    }

    if (zA) epilogue(acc, g_A + (b * NBLK + n) * (BLK * BLK), true, m0, n0, lane);
    else    epilogue(acc, g_U + (b * NBLK + n) * (Ddim * Rdim), false, m0, n0, lane);
}

// ---------------------------------------------------------------------------
// Phase 2: prefix scan on [d][r] state, MLP-32 preload
// ---------------------------------------------------------------------------
__global__ void scan_kernel() {
    int gid = blockIdx.x * 256 + threadIdx.x;   // 131072
    int b = gid >> 14, dr = gid & 16383, r = dr & 127;
    float gdec = g_ptab[128 * 128 + r];         // gamma_r^128
    int base = b * NBLK * 16384 + dr;
    float u[NBLK];
#pragma unroll
    for (int nn = 0; nn < NBLK; nn++) u[nn] = g_U[base + nn * 16384];
    float s = 0.f;
#pragma unroll
    for (int nn = 0; nn < NBLK; nn++) {
        g_S[base + nn * 16384] = s;
        s = fmaf(s, gdec, u[nn]);
    }
}

// ---------------------------------------------------------------------------
// Phase 3: out = A @ H + (Q*g^(i+1)) @ St — one 8-chunk double-buffered loop
// ---------------------------------------------------------------------------
__global__ __launch_bounds__(NTHR, 2) void out_kernel(const float* __restrict__ q,
                                                      const float* __restrict__ h,
                                                      float* __restrict__ out) {
    extern __shared__ __align__(16) char smem[];
    int n = blockIdx.x, b = blockIdx.y;
    int tid = threadIdx.x, wid = tid >> 5, lane = tid & 31;
    int m0 = (wid & 3) * 32, n0 = (wid >> 2) * 64;

    const float* Ablk = g_A + (b * NBLK + n) * (BLK * BLK);
    const float* Sblk = g_S + (b * NBLK + n) * (Ddim * Rdim);
    const float* hblk = h + (b * Wdim + n * BLK) * Ddim;
    const float* qblk = q + (b * Wdim + n * BLK) * Rdim;

    float acc[2][8][4];
    zero_acc(acc);

    // stage chunk 0 (part 1, jc=0) into buf0
    stage_nat32(Ablk, (const float*)0, 0, 0, smem + T_AHI, smem + T_ALO, tid);
    stage_tr32(hblk, false, 0, smem + T_BHI, smem + T_BLO, tid);
    __syncthreads();

#pragma unroll
    for (int c = 0; c < 8; c++) {
        char* cur = smem + (c & 1) * TILBUF;
        gemm32(cur, m0, n0, lane, acc);
        if (c + 1 < 8) {
            int cn = c + 1;
            char* nxt = smem + (cn & 1) * TILBUF;
            if (cn < 4) {
                stage_nat32(Ablk, (const float*)0, 0, cn * 32, nxt + T_AHI, nxt + T_ALO, tid);
                stage_tr32(hblk, false, cn * 32, nxt + T_BHI, nxt + T_BLO, tid);
            } else {
                stage_nat32(qblk, g_ptab, 1, (cn - 4) * 32, nxt + T_AHI, nxt + T_ALO, tid);
                stage_nat32(Sblk, (const float*)0, 0, (cn - 4) * 32, nxt + T_BHI, nxt + T_BLO, tid);
            }
        }
        __syncthreads();
    }

    epilogue(acc, out + (b * Wdim + n * BLK) * Ddim, false, m0, n0, lane);
}

// ---------------------------------------------------------------------------
extern "C" void kernel_launch(void* const* d_in, const int* in_sizes, int n_in,
                              void* d_out, int out_size) {
    const float* q     = (const float*)d_in[0];
    const float* k     = (const float*)d_in[1];
    const float* h     = (const float*)d_in[2];
    const float* gamma = (const float*)d_in[3];
    float* out = (float*)d_out;

    cudaFuncSetAttribute(matAU_kernel, cudaFuncAttributeMaxDynamicSharedMemorySize, SMEM_TOTAL);
    cudaFuncSetAttribute(out_kernel,   cudaFuncAttributeMaxDynamicSharedMemorySize, SMEM_TOTAL);

    pow_kernel<<<257, 128>>>(gamma);
    matAU_kernel<<<dim3(NBLK, Bdim, 2), NTHR, SMEM_TOTAL>>>(q, k, h);
    scan_kernel<<<512, 256>>>();
    out_kernel<<<dim3(NBLK, Bdim), NTHR, SMEM_TOTAL>>>(q, h, out);
}